// round 17
// baseline (speedup 1.0000x reference)
#include <cuda_runtime.h>
#include <math.h>
#include <float.h>

#define B_TOT 8192
#define F 32
#define P 512
#define H 256
#define MS 32           // samples per CTA (2 tiles of 16)
#define T 256           // 4 producer warps + 4 consumer warps

typedef unsigned long long u64;

// ---- packed f32x2 helpers ------------------------------------------------
static __device__ __forceinline__ u64 pack2(float a, float b) {
    u64 r;
    asm("mov.b64 %0, {%1, %2};" : "=l"(r)
        : "r"(__float_as_uint(a)), "r"(__float_as_uint(b)));
    return r;
}
static __device__ __forceinline__ void unpack2(u64 v, float &a, float &b) {
    unsigned lo, hi;
    asm("mov.b64 {%0, %1}, %2;" : "=r"(lo), "=r"(hi) : "l"(v));
    a = __uint_as_float(lo);
    b = __uint_as_float(hi);
}
static __device__ __forceinline__ void fma2(u64 &d, u64 a, u64 b) {
    asm("fma.rn.f32x2 %0, %1, %2, %0;" : "+l"(d) : "l"(a), "l"(b));
}
static __device__ __forceinline__ u64 dbits(double d) {
    return __double_as_longlong(d);
}
// named barriers (warp-specialized producer/consumer handoff)
static __device__ __forceinline__ void bar_arrive(int id, int cnt) {
    asm volatile("bar.arrive %0, %1;" :: "r"(id), "r"(cnt) : "memory");
}
static __device__ __forceinline__ void bar_wait(int id, int cnt) {
    asm volatile("bar.sync %0, %1;" :: "r"(id), "r"(cnt) : "memory");
}

// W1 transposed to [P][H] so consumer LDG is coalesced along neurons.
__device__ float d_W1T[P * H];

__global__ void transpose_w1_kernel(const float* __restrict__ W1) {
    const int k = blockIdx.x;        // 0..511
    const int j = threadIdx.x;       // 0..255
    d_W1T[k * H + j] = W1[j * P + k];
}

// Dynamic SMEM layout (74368 B):
//   [0,     65536)  double2 s_xp[2 tiles][4 groups][512 k]
//                   element .x = packed samples (4g+0, 4g+1) at k
//                   element .y = packed samples (4g+2, 4g+3) at k
//   [65536, 73728)  double  s_wp[32][32]   packed (w,w) mix weights
//   [73728, 73856)  float   s_red[4][8]    LN partials (warp x {sum,sq} x 4)
//   [73856, 74368)  float   s_red2[2][4][16] head partials
#define SMEM_BYTES 74368

__global__ __launch_bounds__(T, 3)
void PhysChemLinearMix_49323404427796_kernel(
    const float* __restrict__ phys,     // [B,F,P]
    const float* __restrict__ ratios,   // [B,F]
    const int*   __restrict__ lengths,  // [B]
    const float* __restrict__ gamma,    // [P]
    const float* __restrict__ beta,     // [P]
    const float* __restrict__ b1,       // [H]
    const float* __restrict__ W2,       // [1,H]
    const float* __restrict__ b2,       // [1]
    float*       __restrict__ out)      // [B,1]
{
    extern __shared__ __align__(16) char smem[];
    double2* s_xp   = reinterpret_cast<double2*>(smem);             // [2][4][512]
    double*  s_wp   = reinterpret_cast<double*>(smem + 65536);      // [32][32]
    float*   s_red  = reinterpret_cast<float*>(smem + 73728);       // [4][8]
    float*   s_red2 = reinterpret_cast<float*>(smem + 73856);       // [2][4][16]

    const int tid  = threadIdx.x;
    const int warp = tid >> 5;
    const int lane = tid & 31;
    const int b0   = blockIdx.x * MS;

    if (tid < 128) {
        // ======================= PRODUCER (warps 0-3) ======================
        // Phase 0: ragged weight normalization for all 32 samples
        #pragma unroll
        for (int s = 0; s < 8; s++) {
            const int m = warp * 8 + s;
            const int b = b0 + m;
            float r = ratios[b * F + lane];
            const int len = lengths[b];
            if (lane >= len) r = 0.f;
            float sum = r;
            #pragma unroll
            for (int off = 16; off > 0; off >>= 1)
                sum += __shfl_xor_sync(0xffffffffu, sum, off);
            const float wn = r / (sum + 1e-8f);
            s_wp[m * F + lane] = __longlong_as_double(pack2(wn, wn));
        }
        bar_wait(3, 128);

        const int q = tid;                       // float4-quad 0..127
        const float4 gv = reinterpret_cast<const float4*>(gamma)[q];
        const float4 bv = reinterpret_cast<const float4*>(beta)[q];

        for (int t = 0; t < 2; t++) {
            for (int g4 = 0; g4 < 4; g4++) {
                float4 rr[4];
                // ---- mix 4 samples (pipelined LDG.128, depth 8) ----
                #pragma unroll
                for (int s4 = 0; s4 < 4; s4++) {
                    const int m  = t * 16 + g4 * 4 + s4;
                    const size_t gs = (size_t)(b0 + m);
                    const double2* base = reinterpret_cast<const double2*>(
                        phys + gs * (F * P)) + q;          // row stride 128
                    u64 a01 = 0ull, a23 = 0ull;
                    double2 buf[2][4];
                    #pragma unroll
                    for (int r = 0; r < 4; r++) buf[0][r] = __ldg(base + r * 128);
                    #pragma unroll
                    for (int g = 0; g < 8; g++) {
                        const int cur = g & 1;
                        if (g < 7) {
                            #pragma unroll
                            for (int r = 0; r < 4; r++)
                                buf[cur ^ 1][r] = __ldg(base + ((g + 1) * 4 + r) * 128);
                        }
                        #pragma unroll
                        for (int r = 0; r < 4; r++) {
                            const u64 w = dbits(s_wp[m * F + g * 4 + r]);
                            fma2(a01, w, dbits(buf[cur][r].x));
                            fma2(a23, w, dbits(buf[cur][r].y));
                        }
                    }
                    float x0, x1, x2, x3;
                    unpack2(a01, x0, x1);
                    unpack2(a23, x2, x3);
                    rr[s4] = make_float4(x0, x1, x2, x3);
                }
                // ---- LN stats for the 4 samples (one barrier round) ----
                float sm[4], sq[4];
                #pragma unroll
                for (int s4 = 0; s4 < 4; s4++) {
                    const float4 v = rr[s4];
                    sm[s4] = v.x + v.y + v.z + v.w;
                    sq[s4] = v.x * v.x + v.y * v.y + v.z * v.z + v.w * v.w;
                }
                #pragma unroll
                for (int off = 16; off > 0; off >>= 1) {
                    #pragma unroll
                    for (int s4 = 0; s4 < 4; s4++) {
                        sm[s4] += __shfl_xor_sync(0xffffffffu, sm[s4], off);
                        sq[s4] += __shfl_xor_sync(0xffffffffu, sq[s4], off);
                    }
                }
                if (lane == 0) {
                    #pragma unroll
                    for (int s4 = 0; s4 < 4; s4++) {
                        s_red[warp * 8 + s4 * 2 + 0] = sm[s4];
                        s_red[warp * 8 + s4 * 2 + 1] = sq[s4];
                    }
                }
                bar_wait(3, 128);
                float mu[4], rs[4];
                #pragma unroll
                for (int s4 = 0; s4 < 4; s4++) {
                    float S = 0.f, Q = 0.f;
                    #pragma unroll
                    for (int w = 0; w < 4; w++) {
                        S += s_red[w * 8 + s4 * 2 + 0];
                        Q += s_red[w * 8 + s4 * 2 + 1];
                    }
                    mu[s4] = S * (1.0f / (float)P);
                    float var = Q * (1.0f / (float)P) - mu[s4] * mu[s4];
                    rs[s4] = rsqrtf(fmaxf(var, 0.f) + 1e-5f);
                }
                bar_wait(3, 128);   // s_red reusable next group
                // ---- normalize + pack pairs + STS.128 (contiguous) ----
                #pragma unroll
                for (int s4 = 0; s4 < 4; s4++) {
                    float4 v = rr[s4];
                    v.x = (v.x - mu[s4]) * rs[s4] * gv.x + bv.x;
                    v.y = (v.y - mu[s4]) * rs[s4] * gv.y + bv.y;
                    v.z = (v.z - mu[s4]) * rs[s4] * gv.z + bv.z;
                    v.w = (v.w - mu[s4]) * rs[s4] * gv.w + bv.w;
                    rr[s4] = v;
                }
                double2* dst = s_xp + (t * 4 + g4) * 512 + 4 * q;
                {
                    double2 d;
                    d.x = __longlong_as_double(pack2(rr[0].x, rr[1].x));
                    d.y = __longlong_as_double(pack2(rr[2].x, rr[3].x));
                    dst[0] = d;
                    d.x = __longlong_as_double(pack2(rr[0].y, rr[1].y));
                    d.y = __longlong_as_double(pack2(rr[2].y, rr[3].y));
                    dst[1] = d;
                    d.x = __longlong_as_double(pack2(rr[0].z, rr[1].z));
                    d.y = __longlong_as_double(pack2(rr[2].z, rr[3].z));
                    dst[2] = d;
                    d.x = __longlong_as_double(pack2(rr[0].w, rr[1].w));
                    d.y = __longlong_as_double(pack2(rr[2].w, rr[3].w));
                    dst[3] = d;
                }
            }
            __threadfence_block();
            bar_arrive(1 + t, 256);     // tile t FULL
        }
    } else {
        // ======================= CONSUMER (warps 4-7) ======================
        const int c = tid - 128;                 // 0..127, neurons (2c, 2c+1)
        const int cw = c >> 5;                   // consumer warp 0..3
        const float2 b1v = reinterpret_cast<const float2*>(b1)[c];
        const float2 w2v = reinterpret_cast<const float2*>(W2)[c];
        const float2* w2p = reinterpret_cast<const float2*>(d_W1T);  // [k*128 + c]

        for (int t = 0; t < 2; t++) {
            bar_wait(1 + t, 256);                // wait tile FULL
            const double2* xp = s_xp + t * 2048; // [4][512]

            u64 acc[16];
            #pragma unroll
            for (int i = 0; i < 16; i++) acc[i] = 0ull;

            float2 wv0 = __ldg(w2p + 0 * 128 + c);
            float2 wv1 = __ldg(w2p + 1 * 128 + c);
            #pragma unroll 4
            for (int k = 0; k < 512; k++) {
                const float2 wv = wv0;
                wv0 = wv1;
                if (k < 510) wv1 = __ldg(w2p + (k + 2) * 128 + c);
                const u64 wA = pack2(wv.x, wv.x);
                const u64 wB = pack2(wv.y, wv.y);
                const double2 x0 = xp[k];
                const double2 x1 = xp[512 + k];
                const double2 x2 = xp[1024 + k];
                const double2 x3 = xp[1536 + k];
                fma2(acc[0], wA, dbits(x0.x)); fma2(acc[1], wA, dbits(x0.y));
                fma2(acc[2], wA, dbits(x1.x)); fma2(acc[3], wA, dbits(x1.y));
                fma2(acc[4], wA, dbits(x2.x)); fma2(acc[5], wA, dbits(x2.y));
                fma2(acc[6], wA, dbits(x3.x)); fma2(acc[7], wA, dbits(x3.y));
                fma2(acc[8],  wB, dbits(x0.x)); fma2(acc[9],  wB, dbits(x0.y));
                fma2(acc[10], wB, dbits(x1.x)); fma2(acc[11], wB, dbits(x1.y));
                fma2(acc[12], wB, dbits(x2.x)); fma2(acc[13], wB, dbits(x2.y));
                fma2(acc[14], wB, dbits(x3.x)); fma2(acc[15], wB, dbits(x3.y));
            }

            // epilogue: ReLU + fold W2, reduce 16 samples over 128 threads
            float v[16];
            #pragma unroll
            for (int p = 0; p < 8; p++) {
                float dA0, dA1, dB0, dB1;
                unpack2(acc[p],     dA0, dA1);
                unpack2(acc[8 + p], dB0, dB1);
                v[2 * p + 0] = fmaxf(dA0 + b1v.x, 0.f) * w2v.x
                             + fmaxf(dB0 + b1v.y, 0.f) * w2v.y;
                v[2 * p + 1] = fmaxf(dA1 + b1v.x, 0.f) * w2v.x
                             + fmaxf(dB1 + b1v.y, 0.f) * w2v.y;
            }
            #pragma unroll
            for (int off = 16; off > 0; off >>= 1) {
                #pragma unroll
                for (int s = 0; s < 16; s++)
                    v[s] += __shfl_xor_sync(0xffffffffu, v[s], off);
            }
            if ((c & 31) == 0) {
                #pragma unroll
                for (int s = 0; s < 16; s++)
                    s_red2[t * 64 + cw * 16 + s] = v[s];
            }
            bar_wait(4, 128);
            if (c < 16) {
                float S = 0.f;
                #pragma unroll
                for (int w = 0; w < 4; w++) S += s_red2[t * 64 + w * 16 + c];
                float y = S + b2[0];
                if (isnan(y))      y = 0.f;                      // nan_to_num
                else if (isinf(y)) y = (y > 0.f) ? FLT_MAX : -FLT_MAX;
                out[b0 + t * 16 + c] = y;
            }
        }
    }
}

extern "C" void kernel_launch(void* const* d_in, const int* in_sizes, int n_in,
                              void* d_out, int out_size) {
    const float* phys    = (const float*)d_in[0];
    const float* ratios  = (const float*)d_in[1];
    const int*   lengths = (const int*)  d_in[2];
    const float* gamma   = (const float*)d_in[3];
    const float* beta    = (const float*)d_in[4];
    const float* W1      = (const float*)d_in[5];
    const float* b1      = (const float*)d_in[6];
    const float* W2      = (const float*)d_in[7];
    const float* b2      = (const float*)d_in[8];
    float* out = (float*)d_out;

    transpose_w1_kernel<<<P, H>>>(W1);

    cudaFuncSetAttribute(PhysChemLinearMix_49323404427796_kernel,
                         cudaFuncAttributeMaxDynamicSharedMemorySize,
                         SMEM_BYTES);
    PhysChemLinearMix_49323404427796_kernel<<<B_TOT / MS, T, SMEM_BYTES>>>(
        phys, ratios, lengths, gamma, beta, b1, W2, b2, out);
}